// round 5
// baseline (speedup 1.0000x reference)
#include <cuda_runtime.h>
#include <math.h>
#include <stdint.h>

// Problem constants
#define SLEN 1024
#define BSZ  32
#define IND  512
#define NH   8
#define HD   64
#define ROWS (SLEN*BSZ)          // 32768
#define NSLOW (NH*(3*HD+1))      // 1544
#define PAIRS (BSZ*NH)           // 256

// ---------------------------------------------------------------------------
// Scratch
// ---------------------------------------------------------------------------
__device__ float g_h[(size_t)ROWS * IND];
__device__ float g_qkvb[(size_t)ROWS * NSLOW];
__device__ float g_q[(size_t)PAIRS * SLEN * HD];    // [p][t][d]
__device__ float g_k[(size_t)PAIRS * SLEN * HD];
__device__ float g_v[(size_t)PAIRS * SLEN * HD];
__device__ float g_beta[(size_t)PAIRS * SLEN];
__device__ float g_kq[(size_t)PAIRS * SLEN];        // k_t . q_t per (p,t)
__device__ float g_o[(size_t)ROWS * IND];

// ---------------------------------------------------------------------------
// 1) LayerNorm: one warp per row of 512
// ---------------------------------------------------------------------------
__global__ __launch_bounds__(256) void ln_kernel(const float* __restrict__ x,
                                                 const float* __restrict__ gam,
                                                 const float* __restrict__ bet,
                                                 float* __restrict__ out)
{
    int warp = threadIdx.x >> 5, lane = threadIdx.x & 31;
    int r = blockIdx.x * 8 + warp;
    const float* xr = x + (size_t)r * IND;
    float v[16], s = 0.f, ss = 0.f;
#pragma unroll
    for (int u = 0; u < 16; u++) {
        float t = xr[u * 32 + lane];
        v[u] = t; s += t; ss += t * t;
    }
#pragma unroll
    for (int o = 16; o > 0; o >>= 1) {
        s  += __shfl_xor_sync(0xffffffffu, s,  o);
        ss += __shfl_xor_sync(0xffffffffu, ss, o);
    }
    float mu  = s * (1.f / IND);
    float var = ss * (1.f / IND) - mu * mu;
    float rs  = rsqrtf(var + 1e-5f);
    float* hr = out + (size_t)r * IND;
#pragma unroll
    for (int u = 0; u < 16; u++) {
        int c = u * 32 + lane;
        hr[c] = (v[u] - mu) * rs * gam[c] + bet[c];
    }
}

// ---------------------------------------------------------------------------
// tf32 helpers
// ---------------------------------------------------------------------------
__device__ __forceinline__ uint32_t f2tf32(float x) {
    uint32_t r;
    asm("cvt.rna.tf32.f32 %0, %1;" : "=r"(r) : "f"(x));
    return r;
}

__device__ __forceinline__ void mma_tf32(float c[4],
                                         uint32_t a0, uint32_t a1, uint32_t a2, uint32_t a3,
                                         uint32_t b0, uint32_t b1)
{
    asm volatile(
        "mma.sync.aligned.m16n8k8.row.col.f32.tf32.tf32.f32 "
        "{%0,%1,%2,%3},{%4,%5,%6,%7},{%8,%9},{%0,%1,%2,%3};\n"
        : "+f"(c[0]), "+f"(c[1]), "+f"(c[2]), "+f"(c[3])
        : "r"(a0), "r"(a1), "r"(a2), "r"(a3), "r"(b0), "r"(b1));
}

// ---------------------------------------------------------------------------
// 2/5) tf32 tensor-core GEMM, 128x128x16 tiles, 256 threads (8 warps)
// ---------------------------------------------------------------------------
template<bool RESID>
__global__ __launch_bounds__(256) void tgemm(const float* __restrict__ A,
                                             const float* __restrict__ B,
                                             const float* __restrict__ X,
                                             float* __restrict__ C,
                                             int M, int N, int K)
{
    __shared__ uint32_t As[2][128][20];
    __shared__ uint32_t Bs[2][16][132];

    int t = threadIdx.x;
    int m0 = blockIdx.y * 128, n0 = blockIdx.x * 128;
    int warp = t >> 5, lane = t & 31;
    int wm = warp >> 2, wn = warp & 3;
    int g = lane >> 2, tg = lane & 3;

    int fa[2] = { t, t + 256 };
    int raA[2], caA[2], raB[2], caB[2];
    bool bval[2];
#pragma unroll
    for (int u = 0; u < 2; u++) {
        raA[u] = fa[u] >> 2;  caA[u] = (fa[u] & 3) * 4;
        raB[u] = fa[u] >> 5;  caB[u] = (fa[u] & 31) * 4;
        bval[u] = (n0 + caB[u]) < N;
    }

    float acc[4][4][4];
#pragma unroll
    for (int im = 0; im < 4; im++)
#pragma unroll
        for (int jn = 0; jn < 4; jn++)
#pragma unroll
            for (int u = 0; u < 4; u++) acc[im][jn][u] = 0.f;

    const int ntiles = K / 16;
    float4 aR[2], bR[2];

#pragma unroll
    for (int u = 0; u < 2; u++) {
        aR[u] = *(const float4*)(A + (size_t)(m0 + raA[u]) * K + caA[u]);
        bR[u] = bval[u] ? *(const float4*)(B + (size_t)raB[u] * N + n0 + caB[u])
                        : make_float4(0.f, 0.f, 0.f, 0.f);
    }
#pragma unroll
    for (int u = 0; u < 2; u++) {
        As[0][raA[u]][caA[u] + 0] = f2tf32(aR[u].x);
        As[0][raA[u]][caA[u] + 1] = f2tf32(aR[u].y);
        As[0][raA[u]][caA[u] + 2] = f2tf32(aR[u].z);
        As[0][raA[u]][caA[u] + 3] = f2tf32(aR[u].w);
        Bs[0][raB[u]][caB[u] + 0] = f2tf32(bR[u].x);
        Bs[0][raB[u]][caB[u] + 1] = f2tf32(bR[u].y);
        Bs[0][raB[u]][caB[u] + 2] = f2tf32(bR[u].z);
        Bs[0][raB[u]][caB[u] + 3] = f2tf32(bR[u].w);
    }
    __syncthreads();

    int buf = 0;
    for (int tile = 0; tile < ntiles; ++tile) {
        if (tile + 1 < ntiles) {
#pragma unroll
            for (int u = 0; u < 2; u++) {
                aR[u] = *(const float4*)(A + (size_t)(m0 + raA[u]) * K + (tile + 1) * 16 + caA[u]);
                bR[u] = bval[u] ? *(const float4*)(B + (size_t)((tile + 1) * 16 + raB[u]) * N + n0 + caB[u])
                                : make_float4(0.f, 0.f, 0.f, 0.f);
            }
        }

#pragma unroll
        for (int kk = 0; kk < 16; kk += 8) {
            uint32_t a[4][4], b[4][2];
#pragma unroll
            for (int im = 0; im < 4; im++) {
                int r0 = wm * 64 + im * 16;
                a[im][0] = As[buf][r0 + g][kk + tg];
                a[im][1] = As[buf][r0 + g + 8][kk + tg];
                a[im][2] = As[buf][r0 + g][kk + tg + 4];
                a[im][3] = As[buf][r0 + g + 8][kk + tg + 4];
            }
#pragma unroll
            for (int jn = 0; jn < 4; jn++) {
                int c0 = wn * 32 + jn * 8;
                b[jn][0] = Bs[buf][kk + tg][c0 + g];
                b[jn][1] = Bs[buf][kk + tg + 4][c0 + g];
            }
#pragma unroll
            for (int im = 0; im < 4; im++)
#pragma unroll
                for (int jn = 0; jn < 4; jn++)
                    mma_tf32(acc[im][jn], a[im][0], a[im][1], a[im][2], a[im][3],
                             b[jn][0], b[jn][1]);
        }

        if (tile + 1 < ntiles) {
            int nb = buf ^ 1;
#pragma unroll
            for (int u = 0; u < 2; u++) {
                As[nb][raA[u]][caA[u] + 0] = f2tf32(aR[u].x);
                As[nb][raA[u]][caA[u] + 1] = f2tf32(aR[u].y);
                As[nb][raA[u]][caA[u] + 2] = f2tf32(aR[u].z);
                As[nb][raA[u]][caA[u] + 3] = f2tf32(aR[u].w);
                Bs[nb][raB[u]][caB[u] + 0] = f2tf32(bR[u].x);
                Bs[nb][raB[u]][caB[u] + 1] = f2tf32(bR[u].y);
                Bs[nb][raB[u]][caB[u] + 2] = f2tf32(bR[u].z);
                Bs[nb][raB[u]][caB[u] + 3] = f2tf32(bR[u].w);
            }
        }
        __syncthreads();
        buf ^= 1;
    }

#pragma unroll
    for (int im = 0; im < 4; im++) {
        int r0 = m0 + wm * 64 + im * 16 + g;
#pragma unroll
        for (int jn = 0; jn < 4; jn++) {
            int col = n0 + wn * 32 + jn * 8 + tg * 2;
            if (col < N) {
                size_t o0 = (size_t)r0 * N + col;
                size_t o1 = (size_t)(r0 + 8) * N + col;
                float v0 = acc[im][jn][0], v1 = acc[im][jn][1];
                float v2 = acc[im][jn][2], v3 = acc[im][jn][3];
                if (RESID) {
                    v0 += X[o0]; v1 += X[o0 + 1];
                    v2 += X[o1]; v3 += X[o1 + 1];
                }
                C[o0] = v0; C[o0 + 1] = v1;
                C[o1] = v2; C[o1 + 1] = v3;
            }
        }
    }
}

// ---------------------------------------------------------------------------
// 3) Activation / repack + precompute kq = k_norm . q_norm
// ---------------------------------------------------------------------------
__global__ __launch_bounds__(256) void act_kernel(const float* __restrict__ qkvb,
                                                  float* __restrict__ qo,
                                                  float* __restrict__ ko,
                                                  float* __restrict__ vo,
                                                  float* __restrict__ bo,
                                                  float* __restrict__ kqo)
{
    int r = blockIdx.x;
    int hh = threadIdx.x >> 5, lane = threadIdx.x & 31;
    int s = r >> 5, b = r & 31;
    int p = b * NH + hh;
    const float* base = qkvb + (size_t)r * NSLOW + hh * (3 * HD + 1);
    size_t dst = ((size_t)p * SLEN + s) * HD;

    float q0 = base[lane], q1 = base[lane + 32];
    q0 = (q0 > 0.f) ? q0 + 1.f : expf(q0);
    q1 = (q1 > 0.f) ? q1 + 1.f : expf(q1);
    float qs = q0 + q1;
#pragma unroll
    for (int o = 16; o > 0; o >>= 1) qs += __shfl_xor_sync(0xffffffffu, qs, o);
    float qi = 1.f / qs;
    q0 *= qi; q1 *= qi;
    qo[dst + lane] = q0; qo[dst + lane + 32] = q1;

    float k0 = base[64 + lane], k1 = base[64 + lane + 32];
    k0 = (k0 > 0.f) ? k0 + 1.f : expf(k0);
    k1 = (k1 > 0.f) ? k1 + 1.f : expf(k1);
    float ks = k0 + k1;
#pragma unroll
    for (int o = 16; o > 0; o >>= 1) ks += __shfl_xor_sync(0xffffffffu, ks, o);
    float ki = 1.f / ks;
    k0 *= ki; k1 *= ki;
    ko[dst + lane] = k0; ko[dst + lane + 32] = k1;

    // kq = sum_d k[d]*q[d]
    float kq = k0 * q0 + k1 * q1;
#pragma unroll
    for (int o = 16; o > 0; o >>= 1) kq += __shfl_xor_sync(0xffffffffu, kq, o);

    vo[dst + lane]      = base[128 + lane];
    vo[dst + lane + 32] = base[128 + lane + 32];
    if (lane == 0) {
        bo[(size_t)p * SLEN + s]  = 1.f / (1.f + expf(-base[192]));
        kqo[(size_t)p * SLEN + s] = kq;
    }
}

// ---------------------------------------------------------------------------
// 4) Delta-rule scan, chunked staging. Both matvecs read W_old:
//      dk = W_old k ; dq = W_old q ; upd = beta (v - dk)
//      o  = dq + upd * (k.q)        [since W_new q = W_old q + upd (k.q)]
//      W += upd k^T
//    -> one shuffle-reduce round per step, W-update off the critical path.
// ---------------------------------------------------------------------------
#define CH 8
#define NCH (SLEN / CH)

__global__ __launch_bounds__(256) void recur_kernel(const float* __restrict__ q,
                                                    const float* __restrict__ k,
                                                    const float* __restrict__ v,
                                                    const float* __restrict__ bta,
                                                    const float* __restrict__ kq,
                                                    float* __restrict__ o)
{
    int p = blockIdx.x;             // b*8 + h
    int t = threadIdx.x;
    int i = t >> 2, jg = t & 3;
    int b = p >> 3, hh = p & 7;

    const float4* kp4  = (const float4*)(k + (size_t)p * SLEN * HD);
    const float4* qp4  = (const float4*)(q + (size_t)p * SLEN * HD);
    const float4* vp4  = (const float4*)(v + (size_t)p * SLEN * HD);
    const float4* bp4  = (const float4*)(bta + (size_t)p * SLEN);
    const float4* kqp4 = (const float4*)(kq + (size_t)p * SLEN);
    float* op = o + (size_t)b * IND + hh * HD + i;

    float W[16];
#pragma unroll
    for (int u = 0; u < 16; u++) W[u] = 0.f;

    __shared__ __align__(16) float sk[2][CH][HD];
    __shared__ __align__(16) float sq[2][CH][HD];
    __shared__ __align__(16) float sv[2][CH][HD];
    __shared__ __align__(16) float sb[2][CH];
    __shared__ __align__(16) float skq[2][CH];

    // staging slots: f0=t in [0,256): k (128 float4) then q (128).
    // f1=t+256 in [256,512): v (f1<384), beta (384,385), kq (386,387).
    int f0 = t, f1 = t + 256;

    float4 r0, r1;
    {
        r0 = (f0 < 128) ? kp4[f0] : qp4[f0 - 128];
        if (f1 < 384)       r1 = vp4[f1 - 256];
        else if (f1 < 386)  r1 = bp4[f1 - 384];
        else if (f1 < 388)  r1 = kqp4[f1 - 386];
        else                r1 = make_float4(0.f, 0.f, 0.f, 0.f);
        if (f0 < 128)      ((float4*)sk[0])[f0] = r0;
        else               ((float4*)sq[0])[f0 - 128] = r0;
        if (f1 < 384)      ((float4*)sv[0])[f1 - 256] = r1;
        else if (f1 < 386) ((float4*)sb[0])[f1 - 384] = r1;
        else if (f1 < 388) ((float4*)skq[0])[f1 - 386] = r1;
    }
    __syncthreads();

    for (int c = 0; c < NCH; ++c) {
        int rb = c & 1;

        // prefetch chunk c+1
        if (c + 1 < NCH) {
            int base4 = (c + 1) * CH * (HD / 4);   // 128 float4 per array per chunk
            r0 = (f0 < 128) ? kp4[base4 + f0] : qp4[base4 + f0 - 128];
            if (f1 < 384)      r1 = vp4[base4 + f1 - 256];
            else if (f1 < 386) r1 = bp4[(c + 1) * 2 + f1 - 384];
            else if (f1 < 388) r1 = kqp4[(c + 1) * 2 + f1 - 386];
        }

#pragma unroll
        for (int sl = 0; sl < CH; ++sl) {
            float kv[16], qv[16];
#pragma unroll
            for (int u = 0; u < 4; u++) {
                *(float4*)&kv[4 * u] = *(const float4*)&sk[rb][sl][jg * 16 + 4 * u];
                *(float4*)&qv[4 * u] = *(const float4*)&sq[rb][sl][jg * 16 + 4 * u];
            }
            float vi  = sv[rb][sl][i];
            float bt  = sb[rb][sl];
            float kqs = skq[rb][sl];

            // both dots from W_old, interleaved (independent chains)
            float a0 = 0.f, a1 = 0.f, a2 = 0.f, a3 = 0.f;
            float c0 = 0.f, c1 = 0.f, c2 = 0.f, c3 = 0.f;
#pragma unroll
            for (int u = 0; u < 4; u++) {
                a0 += W[u]      * kv[u];       c0 += W[u]      * qv[u];
                a1 += W[4 + u]  * kv[4 + u];   c1 += W[4 + u]  * qv[4 + u];
                a2 += W[8 + u]  * kv[8 + u];   c2 += W[8 + u]  * qv[8 + u];
                a3 += W[12 + u] * kv[12 + u];  c3 += W[12 + u] * qv[12 + u];
            }
            float dk = (a0 + a1) + (a2 + a3);
            float dq = (c0 + c1) + (c2 + c3);
            dk += __shfl_xor_sync(0xffffffffu, dk, 1);
            dq += __shfl_xor_sync(0xffffffffu, dq, 1);
            dk += __shfl_xor_sync(0xffffffffu, dk, 2);
            dq += __shfl_xor_sync(0xffffffffu, dq, 2);

            float upd = bt * (vi - dk);
            if (jg == 0) op[(size_t)(c * CH + sl) * BSZ * IND] = dq + upd * kqs;

#pragma unroll
            for (int u = 0; u < 16; u++) W[u] += upd * kv[u];
        }

        __syncthreads();
        if (c + 1 < NCH) {
            int wb = rb ^ 1;
            if (f0 < 128)      ((float4*)sk[wb])[f0] = r0;
            else               ((float4*)sq[wb])[f0 - 128] = r0;
            if (f1 < 384)      ((float4*)sv[wb])[f1 - 256] = r1;
            else if (f1 < 386) ((float4*)sb[wb])[f1 - 384] = r1;
            else if (f1 < 388) ((float4*)skq[wb])[f1 - 386] = r1;
        }
        __syncthreads();
    }
}

// ---------------------------------------------------------------------------
// launch
// ---------------------------------------------------------------------------
extern "C" void kernel_launch(void* const* d_in, const int* in_sizes, int n_in,
                              void* d_out, int out_size)
{
    const float* x   = (const float*)d_in[0];
    const float* gam = (const float*)d_in[1];
    const float* bet = (const float*)d_in[2];
    const float* ws  = (const float*)d_in[3];
    const float* wo  = (const float*)d_in[4];
    float* out = (float*)d_out;

    float *p_h, *p_qkvb, *p_q, *p_k, *p_v, *p_b, *p_kq, *p_o;
    cudaGetSymbolAddress((void**)&p_h,    g_h);
    cudaGetSymbolAddress((void**)&p_qkvb, g_qkvb);
    cudaGetSymbolAddress((void**)&p_q,    g_q);
    cudaGetSymbolAddress((void**)&p_k,    g_k);
    cudaGetSymbolAddress((void**)&p_v,    g_v);
    cudaGetSymbolAddress((void**)&p_b,    g_beta);
    cudaGetSymbolAddress((void**)&p_kq,   g_kq);
    cudaGetSymbolAddress((void**)&p_o,    g_o);

    ln_kernel<<<ROWS / 8, 256>>>(x, gam, bet, p_h);

    {
        dim3 grid((NSLOW + 127) / 128, ROWS / 128);
        tgemm<false><<<grid, 256>>>(p_h, ws, nullptr, p_qkvb, ROWS, NSLOW, IND);
    }

    act_kernel<<<ROWS, 256>>>(p_qkvb, p_q, p_k, p_v, p_b, p_kq);

    recur_kernel<<<PAIRS, 256>>>(p_q, p_k, p_v, p_b, p_kq, p_o);

    {
        dim3 grid(IND / 128, ROWS / 128);
        tgemm<true><<<grid, 256>>>(p_o, wo, x, out, ROWS, IND, IND);
    }
}

// round 7
// speedup vs baseline: 1.1376x; 1.1376x over previous
#include <cuda_runtime.h>
#include <math.h>
#include <stdint.h>

// Problem constants
#define SLEN 1024
#define BSZ  32
#define IND  512
#define NH   8
#define HD   64
#define ROWS (SLEN*BSZ)          // 32768
#define NSLOW (NH*(3*HD+1))      // 1544
#define PAIRS (BSZ*NH)           // 256

// ---------------------------------------------------------------------------
// Scratch
// ---------------------------------------------------------------------------
__device__ float g_h[(size_t)ROWS * IND];
__device__ float g_qkvb[(size_t)ROWS * NSLOW];
__device__ float g_q[(size_t)PAIRS * SLEN * HD];    // [p][t][d]
__device__ float g_k[(size_t)PAIRS * SLEN * HD];
__device__ float g_v[(size_t)PAIRS * SLEN * HD];
__device__ float g_beta[(size_t)PAIRS * SLEN];
__device__ float g_kq[(size_t)PAIRS * SLEN];        // k_t . q_t per (p,t)
__device__ float g_o[(size_t)ROWS * IND];

// ---------------------------------------------------------------------------
// 1) LayerNorm: one warp per row of 512
// ---------------------------------------------------------------------------
__global__ __launch_bounds__(256) void ln_kernel(const float* __restrict__ x,
                                                 const float* __restrict__ gam,
                                                 const float* __restrict__ bet,
                                                 float* __restrict__ out)
{
    int warp = threadIdx.x >> 5, lane = threadIdx.x & 31;
    int r = blockIdx.x * 8 + warp;
    const float* xr = x + (size_t)r * IND;
    float v[16], s = 0.f, ss = 0.f;
#pragma unroll
    for (int u = 0; u < 16; u++) {
        float t = xr[u * 32 + lane];
        v[u] = t; s += t; ss += t * t;
    }
#pragma unroll
    for (int o = 16; o > 0; o >>= 1) {
        s  += __shfl_xor_sync(0xffffffffu, s,  o);
        ss += __shfl_xor_sync(0xffffffffu, ss, o);
    }
    float mu  = s * (1.f / IND);
    float var = ss * (1.f / IND) - mu * mu;
    float rs  = rsqrtf(var + 1e-5f);
    float* hr = out + (size_t)r * IND;
#pragma unroll
    for (int u = 0; u < 16; u++) {
        int c = u * 32 + lane;
        hr[c] = (v[u] - mu) * rs * gam[c] + bet[c];
    }
}

// ---------------------------------------------------------------------------
// mma + cp.async helpers
// ---------------------------------------------------------------------------
__device__ __forceinline__ void mma_tf32(float c[4],
                                         uint32_t a0, uint32_t a1, uint32_t a2, uint32_t a3,
                                         uint32_t b0, uint32_t b1)
{
    asm volatile(
        "mma.sync.aligned.m16n8k8.row.col.f32.tf32.tf32.f32 "
        "{%0,%1,%2,%3},{%4,%5,%6,%7},{%8,%9},{%0,%1,%2,%3};\n"
        : "+f"(c[0]), "+f"(c[1]), "+f"(c[2]), "+f"(c[3])
        : "r"(a0), "r"(a1), "r"(a2), "r"(a3), "r"(b0), "r"(b1));
}

__device__ __forceinline__ void cp16(uint32_t dst, const void* src, bool valid) {
    int sz = valid ? 16 : 0;
    asm volatile("cp.async.cg.shared.global [%0], [%1], 16, %2;\n"
                 :: "r"(dst), "l"(src), "r"(sz));
}
#define CP_COMMIT() asm volatile("cp.async.commit_group;\n" ::: "memory")
#define CP_WAIT1()  asm volatile("cp.async.wait_group 1;\n" ::: "memory")

// ---------------------------------------------------------------------------
// 2/5) tf32 tensor-core GEMM, 128x128x16 tiles, 256 threads, cp.async 3-stage.
//      Raw fp32 bits fed to tf32 mma (HW truncates low mantissa bits).
//      A smem stride 20 (conflict-free frags), B stride 136 (conflict-free).
// ---------------------------------------------------------------------------
#define GSTAGES 3
#define ASTRIDE 20
#define BSTRIDE 136
#define ATILE (128 * ASTRIDE)   // 2560 floats / stage
#define BTILE (16 * BSTRIDE)    // 2176 floats / stage
#define GEMM_SMEM_BYTES (GSTAGES * (ATILE + BTILE) * 4)   // 56832

template<bool RESID>
__global__ __launch_bounds__(256) void tgemm(const float* __restrict__ A,
                                             const float* __restrict__ B,
                                             const float* __restrict__ X,
                                             float* __restrict__ C,
                                             int M, int N, int K)
{
    extern __shared__ float smem[];
    uint32_t smem_u = (uint32_t)__cvta_generic_to_shared(smem);

    int t = threadIdx.x;
    int m0 = blockIdx.y * 128, n0 = blockIdx.x * 128;
    int warp = t >> 5, lane = t & 31;
    int wm = warp >> 2, wn = warp & 3;
    int g = lane >> 2, tg = lane & 3;

    // per-thread load slots: 2 x 16B for A, 2 x 16B for B per tile
    int arow[2], ac4[2], brow[2], bc4[2];
    bool bval[2];
#pragma unroll
    for (int u = 0; u < 2; u++) {
        int fa = t + 256 * u;
        arow[u] = fa >> 2;  ac4[u] = (fa & 3) * 4;      // A tile 128x16
        brow[u] = fa >> 5;  bc4[u] = (fa & 31) * 4;     // B tile 16x128
        bval[u] = (n0 + bc4[u]) < N;
    }

    const int ntiles = K / 16;

    // issue one tile's loads into stage s
    auto issue = [&](int tile, int s) {
#pragma unroll
        for (int u = 0; u < 2; u++) {
            uint32_t ad = smem_u + (uint32_t)((s * ATILE + arow[u] * ASTRIDE + ac4[u]) * 4);
            cp16(ad, A + (size_t)(m0 + arow[u]) * K + tile * 16 + ac4[u], true);
            uint32_t bd = smem_u + (uint32_t)((GSTAGES * ATILE + s * BTILE + brow[u] * BSTRIDE + bc4[u]) * 4);
            cp16(bd, B + (size_t)(tile * 16 + brow[u]) * N + n0 + bc4[u], bval[u]);
        }
        CP_COMMIT();
    };

    float acc[4][4][4];
#pragma unroll
    for (int im = 0; im < 4; im++)
#pragma unroll
        for (int jn = 0; jn < 4; jn++)
#pragma unroll
            for (int u = 0; u < 4; u++) acc[im][jn][u] = 0.f;

    // prologue: stages 0,1 in flight
    issue(0, 0);
    issue(1, 1);
    CP_WAIT1();          // tile 0 landed
    __syncthreads();

    for (int tile = 0; tile < ntiles; ++tile) {
        int s = tile % GSTAGES;
        // stage (tile+2)%3 is free: computed at iter tile-1, barrier passed
        if (tile + 2 < ntiles) issue(tile + 2, (tile + 2) % GSTAGES);
        else                   CP_COMMIT();   // keep group accounting uniform

        const uint32_t* As_ = reinterpret_cast<const uint32_t*>(smem + s * ATILE);
        const uint32_t* Bs_ = reinterpret_cast<const uint32_t*>(smem + GSTAGES * ATILE + s * BTILE);

#pragma unroll
        for (int kk = 0; kk < 16; kk += 8) {
            uint32_t a[4][4], b[4][2];
#pragma unroll
            for (int im = 0; im < 4; im++) {
                int r0 = wm * 64 + im * 16;
                a[im][0] = As_[(r0 + g)     * ASTRIDE + kk + tg];
                a[im][1] = As_[(r0 + g + 8) * ASTRIDE + kk + tg];
                a[im][2] = As_[(r0 + g)     * ASTRIDE + kk + tg + 4];
                a[im][3] = As_[(r0 + g + 8) * ASTRIDE + kk + tg + 4];
            }
#pragma unroll
            for (int jn = 0; jn < 4; jn++) {
                int c0 = wn * 32 + jn * 8;
                b[jn][0] = Bs_[(kk + tg)     * BSTRIDE + c0 + g];
                b[jn][1] = Bs_[(kk + tg + 4) * BSTRIDE + c0 + g];
            }
#pragma unroll
            for (int im = 0; im < 4; im++)
#pragma unroll
                for (int jn = 0; jn < 4; jn++)
                    mma_tf32(acc[im][jn], a[im][0], a[im][1], a[im][2], a[im][3],
                             b[jn][0], b[jn][1]);
        }

        CP_WAIT1();        // next tile landed
        __syncthreads();   // all warps done with stage s; safe to overwrite next iter
    }

    // epilogue
#pragma unroll
    for (int im = 0; im < 4; im++) {
        int r0 = m0 + wm * 64 + im * 16 + g;
#pragma unroll
        for (int jn = 0; jn < 4; jn++) {
            int col = n0 + wn * 32 + jn * 8 + tg * 2;
            if (col < N) {
                size_t o0 = (size_t)r0 * N + col;
                size_t o1 = (size_t)(r0 + 8) * N + col;
                float v0 = acc[im][jn][0], v1 = acc[im][jn][1];
                float v2 = acc[im][jn][2], v3 = acc[im][jn][3];
                if (RESID) {
                    v0 += X[o0]; v1 += X[o0 + 1];
                    v2 += X[o1]; v3 += X[o1 + 1];
                }
                C[o0] = v0; C[o0 + 1] = v1;
                C[o1] = v2; C[o1 + 1] = v3;
            }
        }
    }
}

// ---------------------------------------------------------------------------
// 3) Activation / repack + precompute kq = k_norm . q_norm
// ---------------------------------------------------------------------------
__global__ __launch_bounds__(256) void act_kernel(const float* __restrict__ qkvb,
                                                  float* __restrict__ qo,
                                                  float* __restrict__ ko,
                                                  float* __restrict__ vo,
                                                  float* __restrict__ bo,
                                                  float* __restrict__ kqo)
{
    int r = blockIdx.x;
    int hh = threadIdx.x >> 5, lane = threadIdx.x & 31;
    int s = r >> 5, b = r & 31;
    int p = b * NH + hh;
    const float* base = qkvb + (size_t)r * NSLOW + hh * (3 * HD + 1);
    size_t dst = ((size_t)p * SLEN + s) * HD;

    float q0 = base[lane], q1 = base[lane + 32];
    q0 = (q0 > 0.f) ? q0 + 1.f : expf(q0);
    q1 = (q1 > 0.f) ? q1 + 1.f : expf(q1);
    float qs = q0 + q1;
#pragma unroll
    for (int o = 16; o > 0; o >>= 1) qs += __shfl_xor_sync(0xffffffffu, qs, o);
    float qi = 1.f / qs;
    q0 *= qi; q1 *= qi;
    qo[dst + lane] = q0; qo[dst + lane + 32] = q1;

    float k0 = base[64 + lane], k1 = base[64 + lane + 32];
    k0 = (k0 > 0.f) ? k0 + 1.f : expf(k0);
    k1 = (k1 > 0.f) ? k1 + 1.f : expf(k1);
    float ks = k0 + k1;
#pragma unroll
    for (int o = 16; o > 0; o >>= 1) ks += __shfl_xor_sync(0xffffffffu, ks, o);
    float ki = 1.f / ks;
    k0 *= ki; k1 *= ki;
    ko[dst + lane] = k0; ko[dst + lane + 32] = k1;

    float kq = k0 * q0 + k1 * q1;
#pragma unroll
    for (int o = 16; o > 0; o >>= 1) kq += __shfl_xor_sync(0xffffffffu, kq, o);

    vo[dst + lane]      = base[128 + lane];
    vo[dst + lane + 32] = base[128 + lane + 32];
    if (lane == 0) {
        bo[(size_t)p * SLEN + s]  = 1.f / (1.f + expf(-base[192]));
        kqo[(size_t)p * SLEN + s] = kq;
    }
}

// ---------------------------------------------------------------------------
// 4) Delta-rule scan (unchanged)
// ---------------------------------------------------------------------------
#define CH 8
#define NCH (SLEN / CH)

__global__ __launch_bounds__(256) void recur_kernel(const float* __restrict__ q,
                                                    const float* __restrict__ k,
                                                    const float* __restrict__ v,
                                                    const float* __restrict__ bta,
                                                    const float* __restrict__ kq,
                                                    float* __restrict__ o)
{
    int p = blockIdx.x;             // b*8 + h
    int t = threadIdx.x;
    int i = t >> 2, jg = t & 3;
    int b = p >> 3, hh = p & 7;

    const float4* kp4  = (const float4*)(k + (size_t)p * SLEN * HD);
    const float4* qp4  = (const float4*)(q + (size_t)p * SLEN * HD);
    const float4* vp4  = (const float4*)(v + (size_t)p * SLEN * HD);
    const float4* bp4  = (const float4*)(bta + (size_t)p * SLEN);
    const float4* kqp4 = (const float4*)(kq + (size_t)p * SLEN);
    float* op = o + (size_t)b * IND + hh * HD + i;

    float W[16];
#pragma unroll
    for (int u = 0; u < 16; u++) W[u] = 0.f;

    __shared__ __align__(16) float sk[2][CH][HD];
    __shared__ __align__(16) float sq[2][CH][HD];
    __shared__ __align__(16) float sv[2][CH][HD];
    __shared__ __align__(16) float sb[2][CH];
    __shared__ __align__(16) float skq[2][CH];

    int f0 = t, f1 = t + 256;

    float4 r0, r1;
    {
        r0 = (f0 < 128) ? kp4[f0] : qp4[f0 - 128];
        if (f1 < 384)       r1 = vp4[f1 - 256];
        else if (f1 < 386)  r1 = bp4[f1 - 384];
        else if (f1 < 388)  r1 = kqp4[f1 - 386];
        else                r1 = make_float4(0.f, 0.f, 0.f, 0.f);
        if (f0 < 128)      ((float4*)sk[0])[f0] = r0;
        else               ((float4*)sq[0])[f0 - 128] = r0;
        if (f1 < 384)      ((float4*)sv[0])[f1 - 256] = r1;
        else if (f1 < 386) ((float4*)sb[0])[f1 - 384] = r1;
        else if (f1 < 388) ((float4*)skq[0])[f1 - 386] = r1;
    }
    __syncthreads();

    for (int c = 0; c < NCH; ++c) {
        int rb = c & 1;

        if (c + 1 < NCH) {
            int base4 = (c + 1) * CH * (HD / 4);
            r0 = (f0 < 128) ? kp4[base4 + f0] : qp4[base4 + f0 - 128];
            if (f1 < 384)      r1 = vp4[base4 + f1 - 256];
            else if (f1 < 386) r1 = bp4[(c + 1) * 2 + f1 - 384];
            else if (f1 < 388) r1 = kqp4[(c + 1) * 2 + f1 - 386];
        }

#pragma unroll
        for (int sl = 0; sl < CH; ++sl) {
            float kv[16], qv[16];
#pragma unroll
            for (int u = 0; u < 4; u++) {
                *(float4*)&kv[4 * u] = *(const float4*)&sk[rb][sl][jg * 16 + 4 * u];
                *(float4*)&qv[4 * u] = *(const float4*)&sq[rb][sl][jg * 16 + 4 * u];
            }
            float vi  = sv[rb][sl][i];
            float bt  = sb[rb][sl];
            float kqs = skq[rb][sl];

            float a0 = 0.f, a1 = 0.f, a2 = 0.f, a3 = 0.f;
            float c0 = 0.f, c1 = 0.f, c2 = 0.f, c3 = 0.f;
#pragma unroll
            for (int u = 0; u < 4; u++) {
                a0 += W[u]      * kv[u];       c0 += W[u]      * qv[u];
                a1 += W[4 + u]  * kv[4 + u];   c1 += W[4 + u]  * qv[4 + u];
                a2 += W[8 + u]  * kv[8 + u];   c2 += W[8 + u]  * qv[8 + u];
                a3 += W[12 + u] * kv[12 + u];  c3 += W[12 + u] * qv[12 + u];
            }
            float dk = (a0 + a1) + (a2 + a3);
            float dq = (c0 + c1) + (c2 + c3);
            dk += __shfl_xor_sync(0xffffffffu, dk, 1);
            dq += __shfl_xor_sync(0xffffffffu, dq, 1);
            dk += __shfl_xor_sync(0xffffffffu, dk, 2);
            dq += __shfl_xor_sync(0xffffffffu, dq, 2);

            float upd = bt * (vi - dk);
            if (jg == 0) op[(size_t)(c * CH + sl) * BSZ * IND] = dq + upd * kqs;

#pragma unroll
            for (int u = 0; u < 16; u++) W[u] += upd * kv[u];
        }

        __syncthreads();
        if (c + 1 < NCH) {
            int wb = rb ^ 1;
            if (f0 < 128)      ((float4*)sk[wb])[f0] = r0;
            else               ((float4*)sq[wb])[f0 - 128] = r0;
            if (f1 < 384)      ((float4*)sv[wb])[f1 - 256] = r1;
            else if (f1 < 386) ((float4*)sb[wb])[f1 - 384] = r1;
            else if (f1 < 388) ((float4*)skq[wb])[f1 - 386] = r1;
        }
        __syncthreads();
    }
}

// ---------------------------------------------------------------------------
// launch
// ---------------------------------------------------------------------------
extern "C" void kernel_launch(void* const* d_in, const int* in_sizes, int n_in,
                              void* d_out, int out_size)
{
    const float* x   = (const float*)d_in[0];
    const float* gam = (const float*)d_in[1];
    const float* bet = (const float*)d_in[2];
    const float* ws  = (const float*)d_in[3];
    const float* wo  = (const float*)d_in[4];
    float* out = (float*)d_out;

    float *p_h, *p_qkvb, *p_q, *p_k, *p_v, *p_b, *p_kq, *p_o;
    cudaGetSymbolAddress((void**)&p_h,    g_h);
    cudaGetSymbolAddress((void**)&p_qkvb, g_qkvb);
    cudaGetSymbolAddress((void**)&p_q,    g_q);
    cudaGetSymbolAddress((void**)&p_k,    g_k);
    cudaGetSymbolAddress((void**)&p_v,    g_v);
    cudaGetSymbolAddress((void**)&p_b,    g_beta);
    cudaGetSymbolAddress((void**)&p_kq,   g_kq);
    cudaGetSymbolAddress((void**)&p_o,    g_o);

    // idempotent; no static guard (harness rule), not a stream op (capture-safe)
    cudaFuncSetAttribute(tgemm<false>, cudaFuncAttributeMaxDynamicSharedMemorySize, GEMM_SMEM_BYTES);
    cudaFuncSetAttribute(tgemm<true>,  cudaFuncAttributeMaxDynamicSharedMemorySize, GEMM_SMEM_BYTES);

    ln_kernel<<<ROWS / 8, 256>>>(x, gam, bet, p_h);

    {
        dim3 grid((NSLOW + 127) / 128, ROWS / 128);
        tgemm<false><<<grid, 256, GEMM_SMEM_BYTES>>>(p_h, ws, nullptr, p_qkvb, ROWS, NSLOW, IND);
    }

    act_kernel<<<ROWS, 256>>>(p_qkvb, p_q, p_k, p_v, p_b, p_kq);

    recur_kernel<<<PAIRS, 256>>>(p_q, p_k, p_v, p_b, p_kq, p_o);

    {
        dim3 grid(IND / 128, ROWS / 128);
        tgemm<true><<<grid, 256, GEMM_SMEM_BYTES>>>(p_o, wo, x, out, ROWS, IND, IND);
    }
}